// round 10
// baseline (speedup 1.0000x reference)
#include <cuda_runtime.h>
#include <cstdint>

// ----------------------------------------------------------------------------
// Bidirectional 6-layer GRU, SEQ=512, B=10, H=256, I=128.
// 7 live scan units (fwd L0..L5 + bwd L5); bwd L0..L4 are dead code.
// Units 0..5: 2 clusters of 8 (batch-groups of 5), CTA = 5b x 32j.
// Unit 6:     4 clusters of 8 (2bg x 2bsub),       CTA = {3|2}b x 32j.
// 256 threads / 8 warps, register-resident h-part weights, x-part GEMV in the
// mbarrier-wait shadow. SPLIT TAIL BARRIERS (producer/consumer named bars):
//   bar2 (parts-free): reduce warps arrive after last parts read; all sync
//        before next parts store.
//   bar3 (x-staged):  staging warps arrive after writing x(s+1); all sync at
//        next step head. Staging L2 latency overlaps a full step of compute.
// Per-peer mbarriers; h-exchange via st.async. Inter-unit: g_stage + flags.
// ----------------------------------------------------------------------------

#define SEQ    512
#define BATCH  10
#define NTH    256

typedef unsigned long long ull;

__device__ float g_stage[5][SEQ][BATCH][128];
__device__ int   g_flag[5][2][4][8];

// smem layout
#define WS_BYTES    (3*96*32*16)              // 147456 weights ulonglong2[g][k4][j]
#define XH_OFF      WS_BYTES
#define XH_BYTES    (2*5*384*4)               // 15360 xh[2][5][384]
#define PARTS_OFF   (XH_OFF + XH_BYTES)
#define PARTS_BYTES (8*5*32*16)               // 20480 parts[w][b][j] float4
#define HOWN_OFF    (PARTS_OFF + PARTS_BYTES)
#define HOWN_BYTES  (5*32*4)                  // 640
#define MBAR_OFF    (HOWN_OFF + HOWN_BYTES)   // 16 mbars: [buf][peer]
#define SMEM_TOTAL  (MBAR_OFF + 128)
#define MBAR_DELTA  (MBAR_OFF - XH_OFF)

__device__ __forceinline__ int ld_acquire(const int* p) {
    int v;
    asm volatile("ld.acquire.gpu.b32 %0, [%1];" : "=r"(v) : "l"(p) : "memory");
    return v;
}
__device__ __forceinline__ void st_release(int* p, int v) {
    asm volatile("st.release.gpu.b32 [%0], %1;" :: "l"(p), "r"(v) : "memory");
}
__device__ __forceinline__ void ffma2(ull& d, ull a, ull b) {
    asm volatile("fma.rn.f32x2 %0, %1, %2, %0;" : "+l"(d) : "l"(a), "l"(b));
}
__device__ __forceinline__ void fadd2(ull& d, ull a) {
    asm volatile("add.rn.f32x2 %0, %0, %1;" : "+l"(d) : "l"(a));
}
__device__ __forceinline__ float2 u2f2(ull u) {
    float2 f;
    asm("mov.b64 {%0, %1}, %2;" : "=f"(f.x), "=f"(f.y) : "l"(u));
    return f;
}
__device__ __forceinline__ float sigmoidf_fast(float x) {
    return 1.0f / (1.0f + __expf(-x));
}
__device__ __forceinline__ float tanhf_fast(float x) {
    return fmaf(2.0f, 1.0f / (1.0f + __expf(-2.0f * x)), -1.0f);
}
__device__ __forceinline__ uint32_t smem_u32(const void* p) {
    uint32_t a;
    asm("{ .reg .u64 t; cvta.to.shared.u64 t, %1; cvt.u32.u64 %0, t; }"
        : "=r"(a) : "l"(p));
    return a;
}
__device__ __forceinline__ uint32_t mapa_u32(uint32_t laddr, uint32_t rank) {
    uint32_t r;
    asm("mapa.shared::cluster.u32 %0, %1, %2;" : "=r"(r) : "r"(laddr), "r"(rank));
    return r;
}
__device__ __forceinline__ void st_async_f4_pre(uint32_t raddr, uint32_t rmbar,
                                                float4 v) {
    asm volatile(
        "st.async.shared::cluster.mbarrier::complete_tx::bytes.v4.f32 "
        "[%0], {%2, %3, %4, %5}, [%1];"
        :: "r"(raddr), "r"(rmbar), "f"(v.x), "f"(v.y), "f"(v.z), "f"(v.w)
        : "memory");
}
__device__ __forceinline__ void mbar_init(uint32_t mbar, uint32_t cnt) {
    asm volatile("mbarrier.init.shared.b64 [%0], %1;" :: "r"(mbar), "r"(cnt) : "memory");
}
__device__ __forceinline__ void mbar_expect_tx(uint32_t mbar, uint32_t bytes) {
    asm volatile("mbarrier.arrive.expect_tx.shared.b64 _, [%0], %1;"
                 :: "r"(mbar), "r"(bytes) : "memory");
}
__device__ __forceinline__ void mbar_wait(uint32_t mbar, uint32_t parity) {
    asm volatile(
        "{\n\t.reg .pred P;\n\t"
        "LWAIT_%=:\n\t"
        "mbarrier.try_wait.parity.acquire.cluster.shared::cta.b64 P, [%0], %1, 0x989680;\n\t"
        "@!P bra LWAIT_%=;\n\t}"
        :: "r"(mbar), "r"(parity) : "memory");
}
#define CLUSTER_SYNC() do { \
    asm volatile("barrier.cluster.arrive.aligned;" ::: "memory"); \
    asm volatile("barrier.cluster.wait.aligned;"   ::: "memory"); \
} while (0)
#define BAR_STAGE()      asm volatile("bar.sync 1, 128;" ::: "memory")
#define BAR2_SYNC()      asm volatile("bar.sync 2, 384;" ::: "memory")
#define BAR2_ARRIVE()    asm volatile("bar.arrive 2, 384;" ::: "memory")
#define BAR3_SYNC()      asm volatile("bar.sync 3, 384;" ::: "memory")
#define BAR3_ARRIVE()    asm volatile("bar.arrive 3, 384;" ::: "memory")
#define BAR_PUB()        asm volatile("bar.sync 4, 128;" ::: "memory")

// ============================= unified scan loop ============================
// MODE: 0 = fwd hidden layer (write g_stage), 1 = fwd L5 (out left),
//       2 = bwd L5 (out right, reversed input).
template<int NB, int MODE>
__device__ __forceinline__ void scan_loop(
    const float* __restrict__ x, float* __restrict__ out,
    char* smem, uint32_t smem_base,
    int u, int bg, int boff, int js, int tid)
{
    ulonglong2* ws4   = (ulonglong2*)smem;
    float*      xh    = (float*)(smem + XH_OFF);
    float4*     parts = (float4*)(smem + PARTS_OFF);
    float*      hown  = (float*)(smem + HOWN_OFF);
    float4*     hown4 = (float4*)(smem + HOWN_OFF);
    const uint32_t mbar_base = smem_base + MBAR_OFF;
    const int j0 = js * 32;
    const uint32_t exp_tx = NB * 128;
    const int src_u = (MODE == 2) ? 4 : (u - 1);
    constexpr int C  = NB * 8;     // outputs per reduce warp (warps 0..3)
    constexpr int CB = NB * 2;     // push blocks per reduce warp

    uint32_t rxh[8];
    #pragma unroll
    for (int pe = 0; pe < 8; ++pe)
        rxh[pe] = mapa_u32(smem_base + XH_OFF, (uint32_t)pe);

    // zero h-section of buffer 0
    for (int t = tid; t < NB * 64; t += NTH) {
        int b = t >> 6, q = t & 63;
        *(float4*)&xh[b * 384 + 128 + q * 4] = make_float4(0.f, 0.f, 0.f, 0.f);
    }
    if (tid < 16) {
        mbar_init(mbar_base + tid * 8, 1);
        mbar_expect_tx(mbar_base + tid * 8, exp_tx);
    }
    __syncthreads();
    CLUSTER_SYNC();

    // stage x(sn) into buffer pb — warps 4..7 (threads 128-255)
    auto stage_x = [&](int sn, int pb) {
        float* dst = xh + pb * 1920;
        if (MODE == 0 && u == 0) {
            const float* src = x + ((size_t)sn * BATCH + bg * 5 + boff) * 128;
            for (int t = tid - 128; t < NB * 32; t += 128) {
                int b = t >> 5, q = t & 31;
                *(float4*)&dst[b * 384 + q * 4] = *(const float4*)&src[b * 128 + q * 4];
            }
        } else {
            int ss   = (MODE == 2) ? (SEQ - 1 - sn) : sn;
            int need = (MODE == 2) ? (SEQ - sn) : (sn + 1);
            if (tid >= 128 && tid < 132) {
                const int* fp = &g_flag[src_u][bg][tid - 128][0];
                while (ld_acquire(fp) < need) __nanosleep(128);
            }
            BAR_STAGE();
            const float* src = &g_stage[src_u][ss][bg * 5 + boff][0];
            for (int t = tid - 128; t < NB * 32; t += 128) {
                int b = t >> 5, q = t & 31;
                *(float4*)&dst[b * 384 + q * 4] = *(const float4*)&src[b * 128 + q * 4];
            }
        }
    };

    const int w  = tid >> 5;       // warp 0..7
    const int jl = tid & 31;
    const int xk4s = w * 4;        // x-part: 4 k4 x 3 gates (SMEM weights)
    const int hk4s = 32 + w * 8;   // h-part: 8 k4 x 3 gates (REG weights)
    const uint32_t my_mb0 = mbar_base + (uint32_t)(w * 8);

    // ---- load this warp's h-part weights into registers (once) ----
    ulonglong2 whr[8], whz[8], whn[8];
    #pragma unroll
    for (int t = 0; t < 8; ++t) {
        whr[t] = ws4[(hk4s + t) * 32 + jl];
        whz[t] = ws4[(96 + hk4s + t) * 32 + jl];
        whn[t] = ws4[(192 + hk4s + t) * 32 + jl];
    }

    // ---- initial stage of x(0) into buffer 0 (all threads) ----
    for (int t = tid; t < NB * 32; t += NTH) {
        int b = t >> 5, q = t & 31;
        if (MODE == 0 && u == 0) {
            const float* src = x + ((size_t)(bg * 5 + boff)) * 128;
            *(float4*)&xh[b * 384 + q * 4] = *(const float4*)&src[b * 128 + q * 4];
        } else {
            int ss   = (MODE == 2) ? (SEQ - 1) : 0;
            int need = (MODE == 2) ? SEQ : 1;
            const int* fp = &g_flag[src_u][bg][q >> 3][0];
            while (ld_acquire(fp) < need) __nanosleep(256);
            const float* src = &g_stage[src_u][ss][bg * 5 + boff][0];
            *(float4*)&xh[b * 384 + q * 4] = *(const float4*)&src[b * 128 + q * 4];
        }
    }
    __syncthreads();

    // prime the producer/consumer barriers for iteration 0
    if (tid < 128) BAR2_ARRIVE();
    else           BAR3_ARRIVE();

    uint32_t pha[2] = {0, 0};

    for (int s = 0; s < SEQ; ++s) {
        const int p = s & 1;

        BAR3_SYNC();               // x(s) staged (arrivals from prev tail)
        const ulonglong2* X = (const ulonglong2*)(xh + p * 1920);

        // ---- x-part first (no h dependency): shadows peer-push flight ----
        ull ar[NB], az[NB], anx[NB], anh[NB];
        #pragma unroll
        for (int i = 0; i < NB; ++i) { ar[i] = 0; az[i] = 0; anx[i] = 0; anh[i] = 0; }

        #pragma unroll
        for (int t = 0; t < 4; ++t) {
            int k4 = xk4s + t;
            ulonglong2 wr = ws4[k4 * 32 + jl];
            ulonglong2 wz = ws4[(96 + k4) * 32 + jl];
            ulonglong2 wn = ws4[(192 + k4) * 32 + jl];
            #pragma unroll
            for (int i = 0; i < NB; ++i) {
                ulonglong2 xv = X[i * 96 + k4];
                ffma2(ar[i],  wr.x, xv.x); ffma2(ar[i],  wr.y, xv.y);
                ffma2(az[i],  wz.x, xv.x); ffma2(az[i],  wz.y, xv.y);
                ffma2(anx[i], wn.x, xv.x); ffma2(anx[i], wn.y, xv.y);
            }
        }

        // ---- per-warp wait: only peer w's h-slice feeds this warp ----
        if (s > 0) {
            uint32_t mb = my_mb0 + (uint32_t)(p * 64);
            mbar_wait(mb, pha[p]);
            pha[p] ^= 1;
            if (jl == 0) mbar_expect_tx(mb, exp_tx);
        }

        // ---- h-part: register weights, broadcast X loads only ----
        #pragma unroll
        for (int t = 0; t < 8; ++t) {
            int k4 = hk4s + t;
            #pragma unroll
            for (int i = 0; i < NB; ++i) {
                ulonglong2 xv = X[i * 96 + k4];
                ffma2(ar[i],  whr[t].x, xv.x); ffma2(ar[i],  whr[t].y, xv.y);
                ffma2(az[i],  whz[t].x, xv.x); ffma2(az[i],  whz[t].y, xv.y);
                ffma2(anh[i], whn[t].x, xv.x); ffma2(anh[i], whn[t].y, xv.y);
            }
        }

        BAR2_SYNC();               // parts free (reduce of s-1 done reading)

        #pragma unroll
        for (int i = 0; i < NB; ++i) {
            float2 fr = u2f2(ar[i]),  fz = u2f2(az[i]);
            float2 fx = u2f2(anx[i]), fh = u2f2(anh[i]);
            parts[(w * NB + i) * 32 + jl] =
                make_float4(fr.x + fr.y, fz.x + fz.y, fx.x + fx.y, fh.x + fh.y);
        }
        __syncthreads();   // sync #1: all partials visible

        // ---- warps 0-3: reduce + eltwise + push; warps 4-7: stage x(s+1) ----
        if (tid < 128) {
            #pragma unroll
            for (int t = jl; t < C; t += 32) {
                int out_id = w * C + t;
                int b = out_id >> 5, j = out_id & 31;
                const ulonglong2* pr = (const ulonglong2*)parts;
                ulonglong2 q0 = pr[b * 32 + j];
                ull a01 = q0.x, a23 = q0.y;
                #pragma unroll
                for (int ww = 1; ww < 8; ++ww) {
                    ulonglong2 q = pr[(ww * NB + b) * 32 + j];
                    fadd2(a01, q.x); fadd2(a23, q.y);
                }
                float2 f01 = u2f2(a01), f23 = u2f2(a23);
                float r = sigmoidf_fast(f01.x);
                float z = sigmoidf_fast(f01.y);
                float n = tanhf_fast(f23.x + r * f23.y);
                float hp = xh[p * 1920 + b * 384 + 128 + j0 + j];
                float h  = fmaf(z, hp - n, n);
                hown[b * 32 + j] = h;
                int bglob = bg * 5 + boff + b;
                if (MODE == 1)      out[((size_t)s * BATCH + bglob) * 512 + j0 + j] = h;
                else if (MODE == 2) out[((size_t)s * BATCH + bglob) * 512 + 256 + j0 + j] = h;
                else if (js < 4)    g_stage[u][s][bglob][j0 + j] = h;
            }
            BAR2_ARRIVE();         // parts reads done -> next step may overwrite
            __syncwarp();
            // push this warp's CB j-blocks to all 8 peers
            if (jl < CB && s + 1 < SEQ) {
                int bi = w * CB + jl;          // global j-block 0..NB*8-1
                int b = bi >> 3, j4 = bi & 7;
                float4 v = hown4[b * 8 + j4];
                uint32_t off  = (uint32_t)(((p ^ 1) * 1920 + b * 384 + 128 + j0 + j4 * 4) * 4);
                uint32_t moff = (uint32_t)(MBAR_DELTA + (p ^ 1) * 64 + js * 8);
                #pragma unroll
                for (int pe = 0; pe < 8; ++pe)
                    st_async_f4_pre(rxh[pe] + off, rxh[pe] + moff, v);
            }
            if (MODE == 0 && js < 4) {
                BAR_PUB();         // all 4 writer warps' g_stage stores done
                if (tid == 0) {
                    __threadfence();
                    st_release(&g_flag[u][bg][js][0], s + 1);
                }
            }
        } else {
            if (s + 1 < SEQ) stage_x(s + 1, p ^ 1);
            BAR3_ARRIVE();         // x(s+1) staged
        }
    }
}

// ================================ kernel ====================================
extern "C" __global__ void __launch_bounds__(NTH, 1) __cluster_dims__(8, 1, 1)
gru_persistent_kernel(const float* __restrict__ x,
                      const float* __restrict__ w_ih_l0,
                      const float* __restrict__ w_ih_rest,
                      const float* __restrict__ w_hh,
                      float* __restrict__ out)
{
    extern __shared__ char smem[];
    const uint32_t smem_base = smem_u32(smem);
    const int cta = blockIdx.x;
    const int tid = threadIdx.x;
    const bool isA = (cta < 96);

    int u, bg, js, boff, nb;
    if (isA) {
        u  = cta >> 4;            // 0..5
        bg = (cta >> 3) & 1;
        js = cta & 7;
        boff = 0; nb = 5;
    } else {
        int t = cta - 96;         // unit 6: 2bg x 2bsub x 8js
        u  = 6;
        bg = t >> 4;
        int bsub = (t >> 3) & 1;
        js = t & 7;
        boff = bsub ? 3 : 0;
        nb = bsub ? 2 : 3;
    }
    const int j0 = js * 32;
    const int layer = (u < 6) ? u : 5;
    const int dir   = (u == 6) ? 1 : 0;

    // -------- weights -> smem: ws4[g][k4][j] --------
    const float* Whh = w_hh + (size_t)(layer * 2 + dir) * 768 * 256;
    const float* Wih;
    int pitch;
    if (layer == 0) { Wih = w_ih_l0 + (size_t)dir * 768 * 128; pitch = 128; }
    else            { Wih = w_ih_rest + (size_t)((layer - 1) * 2 + dir) * 768 * 512; pitch = 512; }

    for (int idx = tid; idx < 3 * 96 * 32; idx += NTH) {
        int j  = idx & 31;
        int k4 = (idx >> 5) % 96;
        int g  = idx / (96 * 32);
        int row = g * 256 + j0 + j;
        int k   = k4 * 4;
        const float* src = (k < 128) ? (Wih + (size_t)row * pitch + k)
                                     : (Whh + (size_t)row * 256 + (k - 128));
        ((float4*)smem)[idx] = *(const float4*)src;
    }
    __syncthreads();

    if (isA) {
        if (u < 5) scan_loop<5, 0>(x, out, smem, smem_base, u, bg, boff, js, tid);
        else       scan_loop<5, 1>(x, out, smem, smem_base, u, bg, boff, js, tid);
    } else {
        if (nb == 3) scan_loop<3, 2>(x, out, smem, smem_base, u, bg, boff, js, tid);
        else         scan_loop<2, 2>(x, out, smem, smem_base, u, bg, boff, js, tid);
    }

    CLUSTER_SYNC();
}

extern "C" __global__ void zero_flags_kernel() {
    int t = threadIdx.x;
    if (t < 5 * 2 * 4 * 8) ((int*)g_flag)[t] = 0;
}

extern "C" void kernel_launch(void* const* d_in, const int* in_sizes, int n_in,
                              void* d_out, int out_size) {
    const float* x         = (const float*)d_in[0];
    const float* w_ih_l0   = (const float*)d_in[1];
    const float* w_ih_rest = (const float*)d_in[2];
    const float* w_hh      = (const float*)d_in[3];
    float* out = (float*)d_out;

    cudaFuncSetAttribute(gru_persistent_kernel,
                         cudaFuncAttributeMaxDynamicSharedMemorySize, SMEM_TOTAL);

    zero_flags_kernel<<<1, 320>>>();
    gru_persistent_kernel<<<128, NTH, SMEM_TOTAL>>>(x, w_ih_l0, w_ih_rest, w_hh, out);
}

// round 12
// speedup vs baseline: 1.2085x; 1.2085x over previous
#include <cuda_runtime.h>
#include <cstdint>

// ----------------------------------------------------------------------------
// Bidirectional 6-layer GRU, SEQ=512, B=10, H=256, I=128.
// 7 live scan roles (fwd L0..L5 + bwd L5); bwd L0..L4 are dead code.
// Grid = 96 CTAs = 12 clusters of 8 (6 fwd units x 2 batch-groups of 5).
// ROLE SWITCHING: when fwd unit k (k<5) finishes its 512 steps (~ exactly
// when bwd-L5 may start), its cluster invalidates its mbarriers, reloads
// W(L5,bwd), and re-enters the scan as a bwd-L5 cluster for the single batch
// bg*5+k -> phase 2 runs all 10 independent batch chains concurrently (NB=1).
// R11 crash root-caused: mbarrier.init on still-valid barriers (with pending
// expect_tx) is UB. Fixed: expect_tx re-arm guarded to s+2<SEQ, and explicit
// mbarrier.inval between phases before re-init.
// Per-step machinery = R7 (best known): 8 warps, register-resident h-part
// weights, x-part GEMV in the per-peer mbarrier-wait shadow, warps 0..NB-1
// reduce+eltwise+push (st.async), warps 5-7 stage x(s+1).
// ----------------------------------------------------------------------------

#define SEQ    512
#define BATCH  10
#define NTH    256

typedef unsigned long long ull;

__device__ float g_stage[5][SEQ][BATCH][128];
__device__ int   g_flag[5][2][4][8];

// smem layout
#define WS_BYTES    (3*96*32*16)              // 147456 weights ulonglong2[g][k4][j]
#define XH_OFF      WS_BYTES
#define XH_BYTES    (2*5*384*4)               // 15360 xh[2][5][384]
#define PARTS_OFF   (XH_OFF + XH_BYTES)
#define PARTS_BYTES (8*5*32*16)               // 20480 parts[w][b][j] float4
#define HOWN_OFF    (PARTS_OFF + PARTS_BYTES)
#define HOWN_BYTES  (5*32*4)                  // 640
#define MBAR_OFF    (HOWN_OFF + HOWN_BYTES)   // 16 mbars: [buf][peer]
#define SMEM_TOTAL  (MBAR_OFF + 128)
#define MBAR_DELTA  (MBAR_OFF - XH_OFF)

__device__ __forceinline__ int ld_acquire(const int* p) {
    int v;
    asm volatile("ld.acquire.gpu.b32 %0, [%1];" : "=r"(v) : "l"(p) : "memory");
    return v;
}
__device__ __forceinline__ void st_release(int* p, int v) {
    asm volatile("st.release.gpu.b32 [%0], %1;" :: "l"(p), "r"(v) : "memory");
}
__device__ __forceinline__ void ffma2(ull& d, ull a, ull b) {
    asm volatile("fma.rn.f32x2 %0, %1, %2, %0;" : "+l"(d) : "l"(a), "l"(b));
}
__device__ __forceinline__ void fadd2(ull& d, ull a) {
    asm volatile("add.rn.f32x2 %0, %0, %1;" : "+l"(d) : "l"(a));
}
__device__ __forceinline__ float2 u2f2(ull u) {
    float2 f;
    asm("mov.b64 {%0, %1}, %2;" : "=f"(f.x), "=f"(f.y) : "l"(u));
    return f;
}
__device__ __forceinline__ float sigmoidf_fast(float x) {
    return 1.0f / (1.0f + __expf(-x));
}
__device__ __forceinline__ float tanhf_fast(float x) {
    return fmaf(2.0f, 1.0f / (1.0f + __expf(-2.0f * x)), -1.0f);
}
__device__ __forceinline__ uint32_t smem_u32(const void* p) {
    uint32_t a;
    asm("{ .reg .u64 t; cvta.to.shared.u64 t, %1; cvt.u32.u64 %0, t; }"
        : "=r"(a) : "l"(p));
    return a;
}
__device__ __forceinline__ uint32_t mapa_u32(uint32_t laddr, uint32_t rank) {
    uint32_t r;
    asm("mapa.shared::cluster.u32 %0, %1, %2;" : "=r"(r) : "r"(laddr), "r"(rank));
    return r;
}
__device__ __forceinline__ void st_async_f4_pre(uint32_t raddr, uint32_t rmbar,
                                                float4 v) {
    asm volatile(
        "st.async.shared::cluster.mbarrier::complete_tx::bytes.v4.f32 "
        "[%0], {%2, %3, %4, %5}, [%1];"
        :: "r"(raddr), "r"(rmbar), "f"(v.x), "f"(v.y), "f"(v.z), "f"(v.w)
        : "memory");
}
__device__ __forceinline__ void mbar_init(uint32_t mbar, uint32_t cnt) {
    asm volatile("mbarrier.init.shared.b64 [%0], %1;" :: "r"(mbar), "r"(cnt) : "memory");
}
__device__ __forceinline__ void mbar_inval(uint32_t mbar) {
    asm volatile("mbarrier.inval.shared.b64 [%0];" :: "r"(mbar) : "memory");
}
__device__ __forceinline__ void mbar_expect_tx(uint32_t mbar, uint32_t bytes) {
    asm volatile("mbarrier.arrive.expect_tx.shared.b64 _, [%0], %1;"
                 :: "r"(mbar), "r"(bytes) : "memory");
}
__device__ __forceinline__ void mbar_wait(uint32_t mbar, uint32_t parity) {
    asm volatile(
        "{\n\t.reg .pred P;\n\t"
        "LWAIT_%=:\n\t"
        "mbarrier.try_wait.parity.acquire.cluster.shared::cta.b64 P, [%0], %1, 0x989680;\n\t"
        "@!P bra LWAIT_%=;\n\t}"
        :: "r"(mbar), "r"(parity) : "memory");
}
#define CLUSTER_SYNC() do { \
    asm volatile("barrier.cluster.arrive.aligned;" ::: "memory"); \
    asm volatile("barrier.cluster.wait.aligned;"   ::: "memory"); \
} while (0)
#define BAR_STAGE() asm volatile("bar.sync 1, 96;" ::: "memory")

// -------- weights -> smem: ws4[g][k4][j] (callable twice: role switch) -----
__device__ __forceinline__ void load_weights(
    char* smem, int tid, int layer, int dir, int j0,
    const float* __restrict__ w_ih_l0,
    const float* __restrict__ w_ih_rest,
    const float* __restrict__ w_hh)
{
    const float* Whh = w_hh + (size_t)(layer * 2 + dir) * 768 * 256;
    const float* Wih;
    int pitch;
    if (layer == 0) { Wih = w_ih_l0 + (size_t)dir * 768 * 128; pitch = 128; }
    else            { Wih = w_ih_rest + (size_t)((layer - 1) * 2 + dir) * 768 * 512; pitch = 512; }

    for (int idx = tid; idx < 3 * 96 * 32; idx += NTH) {
        int j  = idx & 31;
        int k4 = (idx >> 5) % 96;
        int g  = idx / (96 * 32);
        int row = g * 256 + j0 + j;
        int k   = k4 * 4;
        const float* src = (k < 128) ? (Wih + (size_t)row * pitch + k)
                                     : (Whh + (size_t)row * 256 + (k - 128));
        ((float4*)smem)[idx] = *(const float4*)src;
    }
}

// ============================= unified scan loop ============================
// MODE: 0 = fwd hidden layer (write g_stage), 1 = fwd L5 (out left),
//       2 = bwd L5 (out right, reversed input).
template<int NB, int MODE>
__device__ __forceinline__ void scan_loop(
    const float* __restrict__ x, float* __restrict__ out,
    char* smem, uint32_t smem_base,
    int u, int bg, int boff, int js, int tid)
{
    ulonglong2* ws4   = (ulonglong2*)smem;
    float*      xh    = (float*)(smem + XH_OFF);
    float4*     parts = (float4*)(smem + PARTS_OFF);
    float*      hown  = (float*)(smem + HOWN_OFF);
    float4*     hown4 = (float4*)(smem + HOWN_OFF);
    const uint32_t mbar_base = smem_base + MBAR_OFF;
    const int j0 = js * 32;
    const uint32_t exp_tx = NB * 128;
    const int src_u = (MODE == 2) ? 4 : (u - 1);

    uint32_t rxh[8];
    #pragma unroll
    for (int pe = 0; pe < 8; ++pe)
        rxh[pe] = mapa_u32(smem_base + XH_OFF, (uint32_t)pe);

    // zero h-section of buffer 0
    for (int t = tid; t < NB * 64; t += NTH) {
        int b = t >> 6, q = t & 63;
        *(float4*)&xh[b * 384 + 128 + q * 4] = make_float4(0.f, 0.f, 0.f, 0.f);
    }
    if (tid < 16) {
        mbar_init(mbar_base + tid * 8, 1);
        mbar_expect_tx(mbar_base + tid * 8, exp_tx);
    }
    __syncthreads();
    CLUSTER_SYNC();   // all peers (re)initialized before any new st.async

    // stage x(sn) into buffer pb — warps 5..7 (threads 160-255)
    auto stage_x = [&](int sn, int pb) {
        float* dst = xh + pb * 1920;
        if (MODE == 0 && u == 0) {
            const float* src = x + ((size_t)sn * BATCH + bg * 5 + boff) * 128;
            for (int t = tid - 160; t < NB * 32; t += 96) {
                int b = t >> 5, q = t & 31;
                *(float4*)&dst[b * 384 + q * 4] = *(const float4*)&src[b * 128 + q * 4];
            }
        } else {
            int ss   = (MODE == 2) ? (SEQ - 1 - sn) : sn;
            int need = (MODE == 2) ? (SEQ - sn) : (sn + 1);
            if (tid >= 224 && tid < 228) {
                const int* fp = &g_flag[src_u][bg][tid - 224][0];
                while (ld_acquire(fp) < need) __nanosleep(128);
            }
            BAR_STAGE();
            const float* src = &g_stage[src_u][ss][bg * 5 + boff][0];
            for (int t = tid - 160; t < NB * 32; t += 96) {
                int b = t >> 5, q = t & 31;
                *(float4*)&dst[b * 384 + q * 4] = *(const float4*)&src[b * 128 + q * 4];
            }
        }
    };

    const int w  = tid >> 5;       // warp 0..7
    const int jl = tid & 31;
    const int xk4s = w * 4;        // x-part: 4 k4 x 3 gates (SMEM weights)
    const int hk4s = 32 + w * 8;   // h-part: 8 k4 x 3 gates (REG weights)
    const uint32_t my_mb0 = mbar_base + (uint32_t)(w * 8);

    // ---- load this warp's h-part weights into registers (once) ----
    ulonglong2 whr[8], whz[8], whn[8];
    #pragma unroll
    for (int t = 0; t < 8; ++t) {
        whr[t] = ws4[(hk4s + t) * 32 + jl];
        whz[t] = ws4[(96 + hk4s + t) * 32 + jl];
        whn[t] = ws4[(192 + hk4s + t) * 32 + jl];
    }

    if (tid >= 160) stage_x(0, 0);
    __syncthreads();

    uint32_t pha[2] = {0, 0};

    for (int s = 0; s < SEQ; ++s) {
        const int p = s & 1;
        const ulonglong2* X = (const ulonglong2*)(xh + p * 1920);

        // ---- x-part first (no h dependency): shadows peer-push flight ----
        ull ar[NB], az[NB], anx[NB], anh[NB];
        #pragma unroll
        for (int i = 0; i < NB; ++i) { ar[i] = 0; az[i] = 0; anx[i] = 0; anh[i] = 0; }

        #pragma unroll
        for (int t = 0; t < 4; ++t) {
            int k4 = xk4s + t;
            ulonglong2 wr = ws4[k4 * 32 + jl];
            ulonglong2 wz = ws4[(96 + k4) * 32 + jl];
            ulonglong2 wn = ws4[(192 + k4) * 32 + jl];
            #pragma unroll
            for (int i = 0; i < NB; ++i) {
                ulonglong2 xv = X[i * 96 + k4];
                ffma2(ar[i],  wr.x, xv.x); ffma2(ar[i],  wr.y, xv.y);
                ffma2(az[i],  wz.x, xv.x); ffma2(az[i],  wz.y, xv.y);
                ffma2(anx[i], wn.x, xv.x); ffma2(anx[i], wn.y, xv.y);
            }
        }

        // ---- per-warp wait: only peer w's h-slice feeds this warp ----
        if (s > 0) {
            uint32_t mb = my_mb0 + (uint32_t)(p * 64);
            mbar_wait(mb, pha[p]);
            pha[p] ^= 1;
            // re-arm only if this buffer is used again (step s+2)
            if (jl == 0 && s + 2 < SEQ) mbar_expect_tx(mb, exp_tx);
        }

        // ---- h-part: register weights, broadcast X loads only ----
        #pragma unroll
        for (int t = 0; t < 8; ++t) {
            int k4 = hk4s + t;
            #pragma unroll
            for (int i = 0; i < NB; ++i) {
                ulonglong2 xv = X[i * 96 + k4];
                ffma2(ar[i],  whr[t].x, xv.x); ffma2(ar[i],  whr[t].y, xv.y);
                ffma2(az[i],  whz[t].x, xv.x); ffma2(az[i],  whz[t].y, xv.y);
                ffma2(anh[i], whn[t].x, xv.x); ffma2(anh[i], whn[t].y, xv.y);
            }
        }

        #pragma unroll
        for (int i = 0; i < NB; ++i) {
            float2 fr = u2f2(ar[i]),  fz = u2f2(az[i]);
            float2 fx = u2f2(anx[i]), fh = u2f2(anh[i]);
            parts[(w * NB + i) * 32 + jl] =
                make_float4(fr.x + fr.y, fz.x + fz.y, fx.x + fx.y, fh.x + fh.y);
        }
        __syncthreads();   // sync #1: all partials in smem

        // ---- warps 0..NB-1: reduce + eltwise + push; warps 5-7: stage ----
        if (tid < NB * 32) {
            int b = tid >> 5, j = tid & 31;
            const ulonglong2* pr = (const ulonglong2*)parts;
            ulonglong2 q0 = pr[b * 32 + j];
            ull a01 = q0.x, a23 = q0.y;
            #pragma unroll
            for (int ww = 1; ww < 8; ++ww) {
                ulonglong2 q = pr[(ww * NB + b) * 32 + j];
                fadd2(a01, q.x); fadd2(a23, q.y);
            }
            float2 f01 = u2f2(a01), f23 = u2f2(a23);
            float r = sigmoidf_fast(f01.x);
            float z = sigmoidf_fast(f01.y);
            float n = tanhf_fast(f23.x + r * f23.y);
            float hp = xh[p * 1920 + b * 384 + 128 + j0 + j];
            float h  = fmaf(z, hp - n, n);
            hown[b * 32 + j] = h;
            int bglob = bg * 5 + boff + b;
            if (MODE == 1)      out[((size_t)s * BATCH + bglob) * 512 + j0 + j] = h;
            else if (MODE == 2) out[((size_t)s * BATCH + bglob) * 512 + 256 + j0 + j] = h;
            else if (js < 4)    g_stage[u][s][bglob][j0 + j] = h;
            __syncwarp();
            if ((j & 3) == 0 && s + 1 < SEQ) {
                float4 v = hown4[b * 8 + (j >> 2)];
                uint32_t off  = (uint32_t)(((p ^ 1) * 1920 + b * 384 + 128 + j0 + j) * 4);
                uint32_t moff = (uint32_t)(MBAR_DELTA + (p ^ 1) * 64 + js * 8);
                #pragma unroll
                for (int pe = 0; pe < 8; ++pe)
                    st_async_f4_pre(rxh[pe] + off, rxh[pe] + moff, v);
            }
        } else if (tid >= 160 && s + 1 < SEQ) {
            stage_x(s + 1, p ^ 1);
        }
        __syncthreads();   // sync #2: staged x visible; parts free for reuse

        if (MODE == 0 && js < 4 && tid == 0) {
            __threadfence();
            st_release(&g_flag[u][bg][js][0], s + 1);
        }
    }
}

// ================================ kernel ====================================
extern "C" __global__ void __launch_bounds__(NTH, 1) __cluster_dims__(8, 1, 1)
gru_persistent_kernel(const float* __restrict__ x,
                      const float* __restrict__ w_ih_l0,
                      const float* __restrict__ w_ih_rest,
                      const float* __restrict__ w_hh,
                      float* __restrict__ out)
{
    extern __shared__ char smem[];
    const uint32_t smem_base = smem_u32(smem);
    const int cta = blockIdx.x;
    const int tid = threadIdx.x;

    const int u  = cta >> 4;          // fwd unit 0..5
    const int bg = (cta >> 3) & 1;    // batch group
    const int js = cta & 7;           // cluster rank / hidden slice
    const int j0 = js * 32;

    // -------- phase 1: forward units --------
    load_weights(smem, tid, u, 0, j0, w_ih_l0, w_ih_rest, w_hh);
    __syncthreads();

    if (u < 5) scan_loop<5, 0>(x, out, smem, smem_base, u, bg, 0, js, tid);
    else       scan_loop<5, 1>(x, out, smem, smem_base, u, bg, 0, js, tid);

    // -------- phase 2: role switch — fwd unit k (k<5) becomes bwd-L5 cluster
    //          for the single batch bg*5+k (NB=1). Unit-k cluster frees at
    //          ~(512+k)*T, exactly when bwd-L5's input (fwd L4 reversed)
    //          becomes available. g_flag[4] reaches 512 -> polls don't spin.
    if (u < 5) {
        __syncthreads();   // all warps past phase-1 reads of ws4/xh/mbars
        if (tid < 16)      // phase-1 mbarriers are quiescent (no pending tx,
            mbar_inval(smem_base + MBAR_OFF + tid * 8);   // re-arm was guarded)
        load_weights(smem, tid, 5, 1, j0, w_ih_l0, w_ih_rest, w_hh);
        __syncthreads();
        scan_loop<1, 2>(x, out, smem, smem_base, 6, bg, u, js, tid);
    }

    CLUSTER_SYNC();
}

extern "C" __global__ void zero_flags_kernel() {
    int t = threadIdx.x;
    if (t < 5 * 2 * 4 * 8) ((int*)g_flag)[t] = 0;
}

extern "C" void kernel_launch(void* const* d_in, const int* in_sizes, int n_in,
                              void* d_out, int out_size) {
    const float* x         = (const float*)d_in[0];
    const float* w_ih_l0   = (const float*)d_in[1];
    const float* w_ih_rest = (const float*)d_in[2];
    const float* w_hh      = (const float*)d_in[3];
    float* out = (float*)d_out;

    cudaFuncSetAttribute(gru_persistent_kernel,
                         cudaFuncAttributeMaxDynamicSharedMemorySize, SMEM_TOTAL);

    zero_flags_kernel<<<1, 320>>>();
    gru_persistent_kernel<<<96, NTH, SMEM_TOTAL>>>(x, w_ih_l0, w_ih_rest, w_hh, out);
}

// round 13
// speedup vs baseline: 1.2733x; 1.0536x over previous
#include <cuda_runtime.h>
#include <cstdint>

// ----------------------------------------------------------------------------
// Bidirectional 6-layer GRU, SEQ=512, B=10, H=256, I=128.
// 7 live scan roles (fwd L0..L5 + bwd L5); bwd L0..L4 are dead code.
// Grid = 96 CTAs = 12 clusters of 8 (6 fwd units x 2 batch-groups of 5).
// Role switching: finished fwd clusters become 10 concurrent NB=1 bwd-L5
// chains (R12). Per-step machinery = R7 + HEAD-ISSUED STAGING (new):
// warps 5-7 issue flag poll + x/g_stage LDGs at the STEP HEAD into registers
// (latency hidden under x-part + mbar wait + h-part), and only STORE to the
// next xh buffer in the tail -> staging L2 latency leaves the sync#2 path.
// g_stage is SEQ-deep (no back-pressure): polls self-align to lag~2, no spin.
// ----------------------------------------------------------------------------

#define SEQ    512
#define BATCH  10
#define NTH    256

typedef unsigned long long ull;

__device__ float g_stage[5][SEQ][BATCH][128];
__device__ int   g_flag[5][2][4][8];

// smem layout
#define WS_BYTES    (3*96*32*16)              // 147456 weights ulonglong2[g][k4][j]
#define XH_OFF      WS_BYTES
#define XH_BYTES    (2*5*384*4)               // 15360 xh[2][5][384]
#define PARTS_OFF   (XH_OFF + XH_BYTES)
#define PARTS_BYTES (8*5*32*16)               // 20480 parts[w][b][j] float4
#define HOWN_OFF    (PARTS_OFF + PARTS_BYTES)
#define HOWN_BYTES  (5*32*4)                  // 640
#define MBAR_OFF    (HOWN_OFF + HOWN_BYTES)   // 16 mbars: [buf][peer]
#define SMEM_TOTAL  (MBAR_OFF + 128)
#define MBAR_DELTA  (MBAR_OFF - XH_OFF)

__device__ __forceinline__ int ld_acquire(const int* p) {
    int v;
    asm volatile("ld.acquire.gpu.b32 %0, [%1];" : "=r"(v) : "l"(p) : "memory");
    return v;
}
__device__ __forceinline__ void st_release(int* p, int v) {
    asm volatile("st.release.gpu.b32 [%0], %1;" :: "l"(p), "r"(v) : "memory");
}
__device__ __forceinline__ void ffma2(ull& d, ull a, ull b) {
    asm volatile("fma.rn.f32x2 %0, %1, %2, %0;" : "+l"(d) : "l"(a), "l"(b));
}
__device__ __forceinline__ void fadd2(ull& d, ull a) {
    asm volatile("add.rn.f32x2 %0, %0, %1;" : "+l"(d) : "l"(a));
}
__device__ __forceinline__ float2 u2f2(ull u) {
    float2 f;
    asm("mov.b64 {%0, %1}, %2;" : "=f"(f.x), "=f"(f.y) : "l"(u));
    return f;
}
__device__ __forceinline__ float sigmoidf_fast(float x) {
    return 1.0f / (1.0f + __expf(-x));
}
__device__ __forceinline__ float tanhf_fast(float x) {
    return fmaf(2.0f, 1.0f / (1.0f + __expf(-2.0f * x)), -1.0f);
}
__device__ __forceinline__ uint32_t smem_u32(const void* p) {
    uint32_t a;
    asm("{ .reg .u64 t; cvta.to.shared.u64 t, %1; cvt.u32.u64 %0, t; }"
        : "=r"(a) : "l"(p));
    return a;
}
__device__ __forceinline__ uint32_t mapa_u32(uint32_t laddr, uint32_t rank) {
    uint32_t r;
    asm("mapa.shared::cluster.u32 %0, %1, %2;" : "=r"(r) : "r"(laddr), "r"(rank));
    return r;
}
__device__ __forceinline__ void st_async_f4_pre(uint32_t raddr, uint32_t rmbar,
                                                float4 v) {
    asm volatile(
        "st.async.shared::cluster.mbarrier::complete_tx::bytes.v4.f32 "
        "[%0], {%2, %3, %4, %5}, [%1];"
        :: "r"(raddr), "r"(rmbar), "f"(v.x), "f"(v.y), "f"(v.z), "f"(v.w)
        : "memory");
}
__device__ __forceinline__ void mbar_init(uint32_t mbar, uint32_t cnt) {
    asm volatile("mbarrier.init.shared.b64 [%0], %1;" :: "r"(mbar), "r"(cnt) : "memory");
}
__device__ __forceinline__ void mbar_inval(uint32_t mbar) {
    asm volatile("mbarrier.inval.shared.b64 [%0];" :: "r"(mbar) : "memory");
}
__device__ __forceinline__ void mbar_expect_tx(uint32_t mbar, uint32_t bytes) {
    asm volatile("mbarrier.arrive.expect_tx.shared.b64 _, [%0], %1;"
                 :: "r"(mbar), "r"(bytes) : "memory");
}
__device__ __forceinline__ void mbar_wait(uint32_t mbar, uint32_t parity) {
    asm volatile(
        "{\n\t.reg .pred P;\n\t"
        "LWAIT_%=:\n\t"
        "mbarrier.try_wait.parity.acquire.cluster.shared::cta.b64 P, [%0], %1, 0x989680;\n\t"
        "@!P bra LWAIT_%=;\n\t}"
        :: "r"(mbar), "r"(parity) : "memory");
}
#define CLUSTER_SYNC() do { \
    asm volatile("barrier.cluster.arrive.aligned;" ::: "memory"); \
    asm volatile("barrier.cluster.wait.aligned;"   ::: "memory"); \
} while (0)
#define BAR_STAGE() asm volatile("bar.sync 1, 96;" ::: "memory")

// -------- weights -> smem: ws4[g][k4][j] (callable twice: role switch) -----
__device__ __forceinline__ void load_weights(
    char* smem, int tid, int layer, int dir, int j0,
    const float* __restrict__ w_ih_l0,
    const float* __restrict__ w_ih_rest,
    const float* __restrict__ w_hh)
{
    const float* Whh = w_hh + (size_t)(layer * 2 + dir) * 768 * 256;
    const float* Wih;
    int pitch;
    if (layer == 0) { Wih = w_ih_l0 + (size_t)dir * 768 * 128; pitch = 128; }
    else            { Wih = w_ih_rest + (size_t)((layer - 1) * 2 + dir) * 768 * 512; pitch = 512; }

    for (int idx = tid; idx < 3 * 96 * 32; idx += NTH) {
        int j  = idx & 31;
        int k4 = (idx >> 5) % 96;
        int g  = idx / (96 * 32);
        int row = g * 256 + j0 + j;
        int k   = k4 * 4;
        const float* src = (k < 128) ? (Wih + (size_t)row * pitch + k)
                                     : (Whh + (size_t)row * 256 + (k - 128));
        ((float4*)smem)[idx] = *(const float4*)src;
    }
}

// ============================= unified scan loop ============================
// MODE: 0 = fwd hidden layer (write g_stage), 1 = fwd L5 (out left),
//       2 = bwd L5 (out right, reversed input).
template<int NB, int MODE>
__device__ __forceinline__ void scan_loop(
    const float* __restrict__ x, float* __restrict__ out,
    char* smem, uint32_t smem_base,
    int u, int bg, int boff, int js, int tid)
{
    ulonglong2* ws4   = (ulonglong2*)smem;
    float*      xh    = (float*)(smem + XH_OFF);
    float4*     parts = (float4*)(smem + PARTS_OFF);
    float*      hown  = (float*)(smem + HOWN_OFF);
    float4*     hown4 = (float4*)(smem + HOWN_OFF);
    const uint32_t mbar_base = smem_base + MBAR_OFF;
    const int j0 = js * 32;
    const uint32_t exp_tx = NB * 128;
    const int src_u = (MODE == 2) ? 4 : (u - 1);

    uint32_t rxh[8];
    #pragma unroll
    for (int pe = 0; pe < 8; ++pe)
        rxh[pe] = mapa_u32(smem_base + XH_OFF, (uint32_t)pe);

    // zero h-section of buffer 0
    for (int t = tid; t < NB * 64; t += NTH) {
        int b = t >> 6, q = t & 63;
        *(float4*)&xh[b * 384 + 128 + q * 4] = make_float4(0.f, 0.f, 0.f, 0.f);
    }
    if (tid < 16) {
        mbar_init(mbar_base + tid * 8, 1);
        mbar_expect_tx(mbar_base + tid * 8, exp_tx);
    }
    __syncthreads();
    CLUSTER_SYNC();   // all peers (re)initialized before any new st.async

    const int w  = tid >> 5;       // warp 0..7
    const int jl = tid & 31;
    const int xk4s = w * 4;        // x-part: 4 k4 x 3 gates (SMEM weights)
    const int hk4s = 32 + w * 8;   // h-part: 8 k4 x 3 gates (REG weights)
    const uint32_t my_mb0 = mbar_base + (uint32_t)(w * 8);
    const int t0 = tid - 160;      // staging index (warps 5-7)

    // ---- load this warp's h-part weights into registers (once) ----
    ulonglong2 whr[8], whz[8], whn[8];
    #pragma unroll
    for (int t = 0; t < 8; ++t) {
        whr[t] = ws4[(hk4s + t) * 32 + jl];
        whz[t] = ws4[(96 + hk4s + t) * 32 + jl];
        whn[t] = ws4[(192 + hk4s + t) * 32 + jl];
    }

    // ---- prologue: stage x(0) into buffer 0 (warps 5-7, full copy) ----
    if (tid >= 160) {
        if (MODE == 0 && u == 0) {
            const float* src = x + ((size_t)(bg * 5 + boff)) * 128;
            for (int t = t0; t < NB * 32; t += 96) {
                int b = t >> 5, q = t & 31;
                *(float4*)&xh[b * 384 + q * 4] = *(const float4*)&src[b * 128 + q * 4];
            }
        } else {
            int ss   = (MODE == 2) ? (SEQ - 1) : 0;
            int need = (MODE == 2) ? SEQ : 1;
            if (tid >= 224 && tid < 228) {
                const int* fp = &g_flag[src_u][bg][tid - 224][0];
                while (ld_acquire(fp) < need) __nanosleep(128);
            }
            BAR_STAGE();
            const float* src = &g_stage[src_u][ss][bg * 5 + boff][0];
            for (int t = t0; t < NB * 32; t += 96) {
                int b = t >> 5, q = t & 31;
                *(float4*)&xh[b * 384 + q * 4] = *(const float4*)&src[b * 128 + q * 4];
            }
        }
    }
    __syncthreads();

    uint32_t pha[2] = {0, 0};

    for (int s = 0; s < SEQ; ++s) {
        const int p = s & 1;
        const ulonglong2* X = (const ulonglong2*)(xh + p * 1920);
        const bool do_stage = (tid >= 160) && (s + 1 < SEQ);

        // ---- HEAD staging: poll flag + issue x(s+1) loads into registers ----
        // (latency hidden under x-part + mbar wait + h-part; store in tail)
        float4 sx0, sx1;
        if (do_stage) {
            if (MODE == 0 && u == 0) {
                const float* src = x + ((size_t)(s + 1) * BATCH + bg * 5 + boff) * 128;
                if (t0 < NB * 32) {
                    int b = t0 >> 5, q = t0 & 31;
                    sx0 = *(const float4*)&src[b * 128 + q * 4];
                }
                if (t0 + 96 < NB * 32) {
                    int t = t0 + 96, b = t >> 5, q = t & 31;
                    sx1 = *(const float4*)&src[b * 128 + q * 4];
                }
            } else {
                int ss   = (MODE == 2) ? (SEQ - 2 - s) : (s + 1);
                int need = (MODE == 2) ? (SEQ - 1 - s) : (s + 2);
                if (tid >= 224 && tid < 228) {
                    const int* fp = &g_flag[src_u][bg][tid - 224][0];
                    while (ld_acquire(fp) < need) __nanosleep(64);
                }
                BAR_STAGE();   // acquire ordering propagated to all 96 threads
                const float* src = &g_stage[src_u][ss][bg * 5 + boff][0];
                if (t0 < NB * 32) {
                    int b = t0 >> 5, q = t0 & 31;
                    sx0 = *(const float4*)&src[b * 128 + q * 4];
                }
                if (t0 + 96 < NB * 32) {
                    int t = t0 + 96, b = t >> 5, q = t & 31;
                    sx1 = *(const float4*)&src[b * 128 + q * 4];
                }
            }
        }

        // ---- x-part (no h dependency): shadows peer-push flight ----
        ull ar[NB], az[NB], anx[NB], anh[NB];
        #pragma unroll
        for (int i = 0; i < NB; ++i) { ar[i] = 0; az[i] = 0; anx[i] = 0; anh[i] = 0; }

        #pragma unroll
        for (int t = 0; t < 4; ++t) {
            int k4 = xk4s + t;
            ulonglong2 wr = ws4[k4 * 32 + jl];
            ulonglong2 wz = ws4[(96 + k4) * 32 + jl];
            ulonglong2 wn = ws4[(192 + k4) * 32 + jl];
            #pragma unroll
            for (int i = 0; i < NB; ++i) {
                ulonglong2 xv = X[i * 96 + k4];
                ffma2(ar[i],  wr.x, xv.x); ffma2(ar[i],  wr.y, xv.y);
                ffma2(az[i],  wz.x, xv.x); ffma2(az[i],  wz.y, xv.y);
                ffma2(anx[i], wn.x, xv.x); ffma2(anx[i], wn.y, xv.y);
            }
        }

        // ---- per-warp wait: only peer w's h-slice feeds this warp ----
        if (s > 0) {
            uint32_t mb = my_mb0 + (uint32_t)(p * 64);
            mbar_wait(mb, pha[p]);
            pha[p] ^= 1;
            // re-arm only if this buffer is used again (step s+2)
            if (jl == 0 && s + 2 < SEQ) mbar_expect_tx(mb, exp_tx);
        }

        // ---- h-part: register weights, broadcast X loads only ----
        #pragma unroll
        for (int t = 0; t < 8; ++t) {
            int k4 = hk4s + t;
            #pragma unroll
            for (int i = 0; i < NB; ++i) {
                ulonglong2 xv = X[i * 96 + k4];
                ffma2(ar[i],  whr[t].x, xv.x); ffma2(ar[i],  whr[t].y, xv.y);
                ffma2(az[i],  whz[t].x, xv.x); ffma2(az[i],  whz[t].y, xv.y);
                ffma2(anh[i], whn[t].x, xv.x); ffma2(anh[i], whn[t].y, xv.y);
            }
        }

        #pragma unroll
        for (int i = 0; i < NB; ++i) {
            float2 fr = u2f2(ar[i]),  fz = u2f2(az[i]);
            float2 fx = u2f2(anx[i]), fh = u2f2(anh[i]);
            parts[(w * NB + i) * 32 + jl] =
                make_float4(fr.x + fr.y, fz.x + fz.y, fx.x + fx.y, fh.x + fh.y);
        }
        __syncthreads();   // sync #1: all partials in smem

        // ---- warps 0..NB-1: reduce + eltwise + push; warps 5-7: STS staged x ----
        if (tid < NB * 32) {
            int b = tid >> 5, j = tid & 31;
            const ulonglong2* pr = (const ulonglong2*)parts;
            ulonglong2 q0 = pr[b * 32 + j];
            ull a01 = q0.x, a23 = q0.y;
            #pragma unroll
            for (int ww = 1; ww < 8; ++ww) {
                ulonglong2 q = pr[(ww * NB + b) * 32 + j];
                fadd2(a01, q.x); fadd2(a23, q.y);
            }
            float2 f01 = u2f2(a01), f23 = u2f2(a23);
            float r = sigmoidf_fast(f01.x);
            float z = sigmoidf_fast(f01.y);
            float n = tanhf_fast(f23.x + r * f23.y);
            float hp = xh[p * 1920 + b * 384 + 128 + j0 + j];
            float h  = fmaf(z, hp - n, n);
            hown[b * 32 + j] = h;
            int bglob = bg * 5 + boff + b;
            if (MODE == 1)      out[((size_t)s * BATCH + bglob) * 512 + j0 + j] = h;
            else if (MODE == 2) out[((size_t)s * BATCH + bglob) * 512 + 256 + j0 + j] = h;
            else if (js < 4)    g_stage[u][s][bglob][j0 + j] = h;
            __syncwarp();
            if ((j & 3) == 0 && s + 1 < SEQ) {
                float4 v = hown4[b * 8 + (j >> 2)];
                uint32_t off  = (uint32_t)(((p ^ 1) * 1920 + b * 384 + 128 + j0 + j) * 4);
                uint32_t moff = (uint32_t)(MBAR_DELTA + (p ^ 1) * 64 + js * 8);
                #pragma unroll
                for (int pe = 0; pe < 8; ++pe)
                    st_async_f4_pre(rxh[pe] + off, rxh[pe] + moff, v);
            }
        } else if (do_stage) {
            float* dst = xh + (p ^ 1) * 1920;
            if (t0 < NB * 32) {
                int b = t0 >> 5, q = t0 & 31;
                *(float4*)&dst[b * 384 + q * 4] = sx0;
            }
            if (t0 + 96 < NB * 32) {
                int t = t0 + 96, b = t >> 5, q = t & 31;
                *(float4*)&dst[b * 384 + q * 4] = sx1;
            }
        }
        __syncthreads();   // sync #2: staged x visible; parts free for reuse

        if (MODE == 0 && js < 4 && tid == 0) {
            __threadfence();
            st_release(&g_flag[u][bg][js][0], s + 1);
        }
    }
}

// ================================ kernel ====================================
extern "C" __global__ void __launch_bounds__(NTH, 1) __cluster_dims__(8, 1, 1)
gru_persistent_kernel(const float* __restrict__ x,
                      const float* __restrict__ w_ih_l0,
                      const float* __restrict__ w_ih_rest,
                      const float* __restrict__ w_hh,
                      float* __restrict__ out)
{
    extern __shared__ char smem[];
    const uint32_t smem_base = smem_u32(smem);
    const int cta = blockIdx.x;
    const int tid = threadIdx.x;

    const int u  = cta >> 4;          // fwd unit 0..5
    const int bg = (cta >> 3) & 1;    // batch group
    const int js = cta & 7;           // cluster rank / hidden slice
    const int j0 = js * 32;

    // -------- phase 1: forward units --------
    load_weights(smem, tid, u, 0, j0, w_ih_l0, w_ih_rest, w_hh);
    __syncthreads();

    if (u < 5) scan_loop<5, 0>(x, out, smem, smem_base, u, bg, 0, js, tid);
    else       scan_loop<5, 1>(x, out, smem, smem_base, u, bg, 0, js, tid);

    // -------- phase 2: role switch — fwd unit k (k<5) becomes bwd-L5 cluster
    //          for the single batch bg*5+k (NB=1).
    if (u < 5) {
        __syncthreads();   // all warps past phase-1 reads of ws4/xh/mbars
        if (tid < 16)      // phase-1 mbarriers quiescent (re-arm was guarded)
            mbar_inval(smem_base + MBAR_OFF + tid * 8);
        load_weights(smem, tid, 5, 1, j0, w_ih_l0, w_ih_rest, w_hh);
        __syncthreads();
        scan_loop<1, 2>(x, out, smem, smem_base, 6, bg, u, js, tid);
    }

    CLUSTER_SYNC();
}

extern "C" __global__ void zero_flags_kernel() {
    int t = threadIdx.x;
    if (t < 5 * 2 * 4 * 8) ((int*)g_flag)[t] = 0;
}

extern "C" void kernel_launch(void* const* d_in, const int* in_sizes, int n_in,
                              void* d_out, int out_size) {
    const float* x         = (const float*)d_in[0];
    const float* w_ih_l0   = (const float*)d_in[1];
    const float* w_ih_rest = (const float*)d_in[2];
    const float* w_hh      = (const float*)d_in[3];
    float* out = (float*)d_out;

    cudaFuncSetAttribute(gru_persistent_kernel,
                         cudaFuncAttributeMaxDynamicSharedMemorySize, SMEM_TOTAL);

    zero_flags_kernel<<<1, 320>>>();
    gru_persistent_kernel<<<96, NTH, SMEM_TOTAL>>>(x, w_ih_l0, w_ih_rest, w_hh, out);
}

// round 14
// speedup vs baseline: 1.4119x; 1.1089x over previous
#include <cuda_runtime.h>
#include <cstdint>

// ----------------------------------------------------------------------------
// Bidirectional 6-layer GRU, SEQ=512, B=10, H=256, I=128.
// 7 live scan roles (fwd L0..L5 + bwd L5); bwd L0..L4 are dead code.
// Grid = 96 CTAs = 12 clusters of 8 (6 fwd units x 2 batch-groups of 5).
// Role switching: finished fwd clusters become 10 concurrent NB=1 bwd-L5
// chains. Per-step machinery: 8 warps, register-resident h-part weights,
// x-part GEMV + head-issued staging LDGs in the mbarrier-wait shadow.
// R14: ONE __syncthreads PER STEP —
//   * parts double-buffered (step parity) -> old sync#2 parts hazard gone
//   * staged-x STS moved to just before sync#1 (LDG latency hidden by GEMV)
//   * tail: reduce -> hown -> syncwarp -> st.async push FIRST -> out STGs
//     -> (MODE0) reduce-only bar.sync + flag release
// ----------------------------------------------------------------------------

#define SEQ    512
#define BATCH  10
#define NTH    256

typedef unsigned long long ull;

__device__ float g_stage[5][SEQ][BATCH][128];
__device__ int   g_flag[5][2][4][8];

// smem layout
#define WS_BYTES    (3*96*32*16)              // 147456 weights ulonglong2[g][k4][j]
#define XH_OFF      WS_BYTES
#define XH_BYTES    (2*5*384*4)               // 15360 xh[2][5][384]
#define PARTS_OFF   (XH_OFF + XH_BYTES)
#define PARTS_BYTES (2*8*5*32*16)             // 40960 parts[2][w][b][j] float4
#define HOWN_OFF    (PARTS_OFF + PARTS_BYTES)
#define HOWN_BYTES  (5*32*4)                  // 640
#define MBAR_OFF    (HOWN_OFF + HOWN_BYTES)   // 16 mbars: [buf][peer]
#define SMEM_TOTAL  (MBAR_OFF + 128)          // 204544
#define MBAR_DELTA  (MBAR_OFF - XH_OFF)

__device__ __forceinline__ int ld_acquire(const int* p) {
    int v;
    asm volatile("ld.acquire.gpu.b32 %0, [%1];" : "=r"(v) : "l"(p) : "memory");
    return v;
}
__device__ __forceinline__ void st_release(int* p, int v) {
    asm volatile("st.release.gpu.b32 [%0], %1;" :: "l"(p), "r"(v) : "memory");
}
__device__ __forceinline__ void ffma2(ull& d, ull a, ull b) {
    asm volatile("fma.rn.f32x2 %0, %1, %2, %0;" : "+l"(d) : "l"(a), "l"(b));
}
__device__ __forceinline__ void fadd2(ull& d, ull a) {
    asm volatile("add.rn.f32x2 %0, %0, %1;" : "+l"(d) : "l"(a));
}
__device__ __forceinline__ float2 u2f2(ull u) {
    float2 f;
    asm("mov.b64 {%0, %1}, %2;" : "=f"(f.x), "=f"(f.y) : "l"(u));
    return f;
}
__device__ __forceinline__ float sigmoidf_fast(float x) {
    return 1.0f / (1.0f + __expf(-x));
}
__device__ __forceinline__ float tanhf_fast(float x) {
    return fmaf(2.0f, 1.0f / (1.0f + __expf(-2.0f * x)), -1.0f);
}
__device__ __forceinline__ uint32_t smem_u32(const void* p) {
    uint32_t a;
    asm("{ .reg .u64 t; cvta.to.shared.u64 t, %1; cvt.u32.u64 %0, t; }"
        : "=r"(a) : "l"(p));
    return a;
}
__device__ __forceinline__ uint32_t mapa_u32(uint32_t laddr, uint32_t rank) {
    uint32_t r;
    asm("mapa.shared::cluster.u32 %0, %1, %2;" : "=r"(r) : "r"(laddr), "r"(rank));
    return r;
}
__device__ __forceinline__ void st_async_f4_pre(uint32_t raddr, uint32_t rmbar,
                                                float4 v) {
    asm volatile(
        "st.async.shared::cluster.mbarrier::complete_tx::bytes.v4.f32 "
        "[%0], {%2, %3, %4, %5}, [%1];"
        :: "r"(raddr), "r"(rmbar), "f"(v.x), "f"(v.y), "f"(v.z), "f"(v.w)
        : "memory");
}
__device__ __forceinline__ void mbar_init(uint32_t mbar, uint32_t cnt) {
    asm volatile("mbarrier.init.shared.b64 [%0], %1;" :: "r"(mbar), "r"(cnt) : "memory");
}
__device__ __forceinline__ void mbar_inval(uint32_t mbar) {
    asm volatile("mbarrier.inval.shared.b64 [%0];" :: "r"(mbar) : "memory");
}
__device__ __forceinline__ void mbar_expect_tx(uint32_t mbar, uint32_t bytes) {
    asm volatile("mbarrier.arrive.expect_tx.shared.b64 _, [%0], %1;"
                 :: "r"(mbar), "r"(bytes) : "memory");
}
__device__ __forceinline__ void mbar_wait(uint32_t mbar, uint32_t parity) {
    asm volatile(
        "{\n\t.reg .pred P;\n\t"
        "LWAIT_%=:\n\t"
        "mbarrier.try_wait.parity.acquire.cluster.shared::cta.b64 P, [%0], %1, 0x989680;\n\t"
        "@!P bra LWAIT_%=;\n\t}"
        :: "r"(mbar), "r"(parity) : "memory");
}
#define CLUSTER_SYNC() do { \
    asm volatile("barrier.cluster.arrive.aligned;" ::: "memory"); \
    asm volatile("barrier.cluster.wait.aligned;"   ::: "memory"); \
} while (0)
#define BAR_STAGE() asm volatile("bar.sync 1, 96;"  ::: "memory")
#define BAR_RED()   asm volatile("bar.sync 4, 160;" ::: "memory")

// -------- weights -> smem: ws4[g][k4][j] (callable twice: role switch) -----
__device__ __forceinline__ void load_weights(
    char* smem, int tid, int layer, int dir, int j0,
    const float* __restrict__ w_ih_l0,
    const float* __restrict__ w_ih_rest,
    const float* __restrict__ w_hh)
{
    const float* Whh = w_hh + (size_t)(layer * 2 + dir) * 768 * 256;
    const float* Wih;
    int pitch;
    if (layer == 0) { Wih = w_ih_l0 + (size_t)dir * 768 * 128; pitch = 128; }
    else            { Wih = w_ih_rest + (size_t)((layer - 1) * 2 + dir) * 768 * 512; pitch = 512; }

    for (int idx = tid; idx < 3 * 96 * 32; idx += NTH) {
        int j  = idx & 31;
        int k4 = (idx >> 5) % 96;
        int g  = idx / (96 * 32);
        int row = g * 256 + j0 + j;
        int k   = k4 * 4;
        const float* src = (k < 128) ? (Wih + (size_t)row * pitch + k)
                                     : (Whh + (size_t)row * 256 + (k - 128));
        ((float4*)smem)[idx] = *(const float4*)src;
    }
}

// ============================= unified scan loop ============================
// MODE: 0 = fwd hidden layer (write g_stage), 1 = fwd L5 (out left),
//       2 = bwd L5 (out right, reversed input).
template<int NB, int MODE>
__device__ __forceinline__ void scan_loop(
    const float* __restrict__ x, float* __restrict__ out,
    char* smem, uint32_t smem_base,
    int u, int bg, int boff, int js, int tid)
{
    ulonglong2* ws4   = (ulonglong2*)smem;
    float*      xh    = (float*)(smem + XH_OFF);
    float4*     parts = (float4*)(smem + PARTS_OFF);   // [2][8][5][32]
    float*      hown  = (float*)(smem + HOWN_OFF);
    float4*     hown4 = (float4*)(smem + HOWN_OFF);
    const uint32_t mbar_base = smem_base + MBAR_OFF;
    const int j0 = js * 32;
    const uint32_t exp_tx = NB * 128;
    const int src_u = (MODE == 2) ? 4 : (u - 1);

    uint32_t rxh[8];
    #pragma unroll
    for (int pe = 0; pe < 8; ++pe)
        rxh[pe] = mapa_u32(smem_base + XH_OFF, (uint32_t)pe);

    // zero h-section of buffer 0
    for (int t = tid; t < NB * 64; t += NTH) {
        int b = t >> 6, q = t & 63;
        *(float4*)&xh[b * 384 + 128 + q * 4] = make_float4(0.f, 0.f, 0.f, 0.f);
    }
    if (tid < 16) {
        mbar_init(mbar_base + tid * 8, 1);
        mbar_expect_tx(mbar_base + tid * 8, exp_tx);
    }
    __syncthreads();
    CLUSTER_SYNC();   // all peers (re)initialized before any new st.async

    const int w  = tid >> 5;       // warp 0..7
    const int jl = tid & 31;
    const int xk4s = w * 4;        // x-part: 4 k4 x 3 gates (SMEM weights)
    const int hk4s = 32 + w * 8;   // h-part: 8 k4 x 3 gates (REG weights)
    const uint32_t my_mb0 = mbar_base + (uint32_t)(w * 8);
    const int t0 = tid - 160;      // staging index (warps 5-7)

    // ---- load this warp's h-part weights into registers (once) ----
    ulonglong2 whr[8], whz[8], whn[8];
    #pragma unroll
    for (int t = 0; t < 8; ++t) {
        whr[t] = ws4[(hk4s + t) * 32 + jl];
        whz[t] = ws4[(96 + hk4s + t) * 32 + jl];
        whn[t] = ws4[(192 + hk4s + t) * 32 + jl];
    }

    // ---- prologue: stage x(0) into buffer 0 (warps 5-7, full copy) ----
    if (tid >= 160) {
        if (MODE == 0 && u == 0) {
            const float* src = x + ((size_t)(bg * 5 + boff)) * 128;
            for (int t = t0; t < NB * 32; t += 96) {
                int b = t >> 5, q = t & 31;
                *(float4*)&xh[b * 384 + q * 4] = *(const float4*)&src[b * 128 + q * 4];
            }
        } else {
            int ss   = (MODE == 2) ? (SEQ - 1) : 0;
            int need = (MODE == 2) ? SEQ : 1;
            if (tid >= 224 && tid < 228) {
                const int* fp = &g_flag[src_u][bg][tid - 224][0];
                while (ld_acquire(fp) < need) __nanosleep(128);
            }
            BAR_STAGE();
            const float* src = &g_stage[src_u][ss][bg * 5 + boff][0];
            for (int t = t0; t < NB * 32; t += 96) {
                int b = t >> 5, q = t & 31;
                *(float4*)&xh[b * 384 + q * 4] = *(const float4*)&src[b * 128 + q * 4];
            }
        }
    }
    __syncthreads();

    uint32_t pha[2] = {0, 0};

    for (int s = 0; s < SEQ; ++s) {
        const int p = s & 1;
        const ulonglong2* X = (const ulonglong2*)(xh + p * 1920);
        float4* pb = parts + p * 1280;                 // parts buffer this step
        const bool do_stage = (tid >= 160) && (s + 1 < SEQ);

        // ---- HEAD staging: poll flag + issue x(s+1) loads into registers ----
        float4 sx0, sx1;
        if (do_stage) {
            if (MODE == 0 && u == 0) {
                const float* src = x + ((size_t)(s + 1) * BATCH + bg * 5 + boff) * 128;
                if (t0 < NB * 32) {
                    int b = t0 >> 5, q = t0 & 31;
                    sx0 = *(const float4*)&src[b * 128 + q * 4];
                }
                if (t0 + 96 < NB * 32) {
                    int t = t0 + 96, b = t >> 5, q = t & 31;
                    sx1 = *(const float4*)&src[b * 128 + q * 4];
                }
            } else {
                int ss   = (MODE == 2) ? (SEQ - 2 - s) : (s + 1);
                int need = (MODE == 2) ? (SEQ - 1 - s) : (s + 2);
                if (tid >= 224 && tid < 228) {
                    const int* fp = &g_flag[src_u][bg][tid - 224][0];
                    while (ld_acquire(fp) < need) __nanosleep(64);
                }
                BAR_STAGE();   // acquire ordering propagated to all 96 threads
                const float* src = &g_stage[src_u][ss][bg * 5 + boff][0];
                if (t0 < NB * 32) {
                    int b = t0 >> 5, q = t0 & 31;
                    sx0 = *(const float4*)&src[b * 128 + q * 4];
                }
                if (t0 + 96 < NB * 32) {
                    int t = t0 + 96, b = t >> 5, q = t & 31;
                    sx1 = *(const float4*)&src[b * 128 + q * 4];
                }
            }
        }

        // ---- x-part (no h dependency): shadows peer-push flight ----
        ull ar[NB], az[NB], anx[NB], anh[NB];
        #pragma unroll
        for (int i = 0; i < NB; ++i) { ar[i] = 0; az[i] = 0; anx[i] = 0; anh[i] = 0; }

        #pragma unroll
        for (int t = 0; t < 4; ++t) {
            int k4 = xk4s + t;
            ulonglong2 wr = ws4[k4 * 32 + jl];
            ulonglong2 wz = ws4[(96 + k4) * 32 + jl];
            ulonglong2 wn = ws4[(192 + k4) * 32 + jl];
            #pragma unroll
            for (int i = 0; i < NB; ++i) {
                ulonglong2 xv = X[i * 96 + k4];
                ffma2(ar[i],  wr.x, xv.x); ffma2(ar[i],  wr.y, xv.y);
                ffma2(az[i],  wz.x, xv.x); ffma2(az[i],  wz.y, xv.y);
                ffma2(anx[i], wn.x, xv.x); ffma2(anx[i], wn.y, xv.y);
            }
        }

        // ---- per-warp wait: only peer w's h-slice feeds this warp ----
        if (s > 0) {
            uint32_t mb = my_mb0 + (uint32_t)(p * 64);
            mbar_wait(mb, pha[p]);
            pha[p] ^= 1;
            if (jl == 0 && s + 2 < SEQ) mbar_expect_tx(mb, exp_tx);
        }

        // ---- h-part: register weights, broadcast X loads only ----
        #pragma unroll
        for (int t = 0; t < 8; ++t) {
            int k4 = hk4s + t;
            #pragma unroll
            for (int i = 0; i < NB; ++i) {
                ulonglong2 xv = X[i * 96 + k4];
                ffma2(ar[i],  whr[t].x, xv.x); ffma2(ar[i],  whr[t].y, xv.y);
                ffma2(az[i],  whz[t].x, xv.x); ffma2(az[i],  whz[t].y, xv.y);
                ffma2(anh[i], whn[t].x, xv.x); ffma2(anh[i], whn[t].y, xv.y);
            }
        }

        #pragma unroll
        for (int i = 0; i < NB; ++i) {
            float2 fr = u2f2(ar[i]),  fz = u2f2(az[i]);
            float2 fx = u2f2(anx[i]), fh = u2f2(anh[i]);
            pb[(w * NB + i) * 32 + jl] =
                make_float4(fr.x + fr.y, fz.x + fz.y, fx.x + fx.y, fh.x + fh.y);
        }

        // ---- staged x -> xh[p^1].x (LDG data arrived during GEMV) ----
        if (do_stage) {
            float* dst = xh + (p ^ 1) * 1920;
            if (t0 < NB * 32) {
                int b = t0 >> 5, q = t0 & 31;
                *(float4*)&dst[b * 384 + q * 4] = sx0;
            }
            if (t0 + 96 < NB * 32) {
                int t = t0 + 96, b = t >> 5, q = t & 31;
                *(float4*)&dst[b * 384 + q * 4] = sx1;
            }
        }
        __syncthreads();   // THE step barrier: partials + staged x visible

        // ---- warps 0..NB-1: reduce + eltwise + push-first + outputs ----
        if (tid < NB * 32) {
            int b = tid >> 5, j = tid & 31;
            const ulonglong2* pr = (const ulonglong2*)pb;
            ulonglong2 q0 = pr[b * 32 + j];
            ull a01 = q0.x, a23 = q0.y;
            #pragma unroll
            for (int ww = 1; ww < 8; ++ww) {
                ulonglong2 q = pr[(ww * NB + b) * 32 + j];
                fadd2(a01, q.x); fadd2(a23, q.y);
            }
            float2 f01 = u2f2(a01), f23 = u2f2(a23);
            float r = sigmoidf_fast(f01.x);
            float z = sigmoidf_fast(f01.y);
            float n = tanhf_fast(f23.x + r * f23.y);
            float hp = xh[p * 1920 + b * 384 + 128 + j0 + j];
            float h  = fmaf(z, hp - n, n);
            hown[b * 32 + j] = h;
            __syncwarp();
            // push FIRST: peers' mbar_wait is the inter-CTA critical path
            if ((j & 3) == 0 && s + 1 < SEQ) {
                float4 v = hown4[b * 8 + (j >> 2)];
                uint32_t off  = (uint32_t)(((p ^ 1) * 1920 + b * 384 + 128 + j0 + j) * 4);
                uint32_t moff = (uint32_t)(MBAR_DELTA + (p ^ 1) * 64 + js * 8);
                #pragma unroll
                for (int pe = 0; pe < 8; ++pe)
                    st_async_f4_pre(rxh[pe] + off, rxh[pe] + moff, v);
            }
            int bglob = bg * 5 + boff + b;
            if (MODE == 1)      out[((size_t)s * BATCH + bglob) * 512 + j0 + j] = h;
            else if (MODE == 2) out[((size_t)s * BATCH + bglob) * 512 + 256 + j0 + j] = h;
            else if (js < 4)    g_stage[u][s][bglob][j0 + j] = h;
        }
        // publish: reduce-warp-only barrier orders all g_stage stores
        if (MODE == 0 && tid < 160) {
            BAR_RED();
            if (js < 4 && tid == 0) {
                __threadfence();
                st_release(&g_flag[u][bg][js][0], s + 1);
            }
        }
    }
}

// ================================ kernel ====================================
extern "C" __global__ void __launch_bounds__(NTH, 1) __cluster_dims__(8, 1, 1)
gru_persistent_kernel(const float* __restrict__ x,
                      const float* __restrict__ w_ih_l0,
                      const float* __restrict__ w_ih_rest,
                      const float* __restrict__ w_hh,
                      float* __restrict__ out)
{
    extern __shared__ char smem[];
    const uint32_t smem_base = smem_u32(smem);
    const int cta = blockIdx.x;
    const int tid = threadIdx.x;

    const int u  = cta >> 4;          // fwd unit 0..5
    const int bg = (cta >> 3) & 1;    // batch group
    const int js = cta & 7;           // cluster rank / hidden slice
    const int j0 = js * 32;

    // -------- phase 1: forward units --------
    load_weights(smem, tid, u, 0, j0, w_ih_l0, w_ih_rest, w_hh);
    __syncthreads();

    if (u < 5) scan_loop<5, 0>(x, out, smem, smem_base, u, bg, 0, js, tid);
    else       scan_loop<5, 1>(x, out, smem, smem_base, u, bg, 0, js, tid);

    // -------- phase 2: role switch — fwd unit k (k<5) becomes bwd-L5 cluster
    //          for the single batch bg*5+k (NB=1).
    if (u < 5) {
        __syncthreads();   // all warps past phase-1 reads of ws4/xh/mbars
        if (tid < 16)      // phase-1 mbarriers quiescent (re-arm was guarded)
            mbar_inval(smem_base + MBAR_OFF + tid * 8);
        load_weights(smem, tid, 5, 1, j0, w_ih_l0, w_ih_rest, w_hh);
        __syncthreads();
        scan_loop<1, 2>(x, out, smem, smem_base, 6, bg, u, js, tid);
    }

    CLUSTER_SYNC();
}

extern "C" __global__ void zero_flags_kernel() {
    int t = threadIdx.x;
    if (t < 5 * 2 * 4 * 8) ((int*)g_flag)[t] = 0;
}

extern "C" void kernel_launch(void* const* d_in, const int* in_sizes, int n_in,
                              void* d_out, int out_size) {
    const float* x         = (const float*)d_in[0];
    const float* w_ih_l0   = (const float*)d_in[1];
    const float* w_ih_rest = (const float*)d_in[2];
    const float* w_hh      = (const float*)d_in[3];
    float* out = (float*)d_out;

    cudaFuncSetAttribute(gru_persistent_kernel,
                         cudaFuncAttributeMaxDynamicSharedMemorySize, SMEM_TOTAL);

    zero_flags_kernel<<<1, 320>>>();
    gru_persistent_kernel<<<96, NTH, SMEM_TOTAL>>>(x, w_ih_l0, w_ih_rest, w_hh, out);
}